// round 6
// baseline (speedup 1.0000x reference)
#include <cuda_runtime.h>
#include <math.h>

// ---------------------------------------------------------------------------
// Problem constants
// ---------------------------------------------------------------------------
#define S_LEN   2048
#define D_DIM   64
#define N_HEADS 8
#define B_SZ    2
#define BH      (B_SZ * N_HEADS)          // 16
#define NTOK    (B_SZ * S_LEN)            // 4096
#define HD      (N_HEADS * D_DIM)         // 512
#define SCALE_F 0.125f                    // 1/sqrt(64)

// ---------------------------------------------------------------------------
// Scratch (device globals -- no allocations allowed)
// ---------------------------------------------------------------------------
__device__ float g_qh[BH * S_LEN * D_DIM];   // [b,h,s,d] roped Q
__device__ float g_kh[BH * S_LEN * D_DIM];   // [b,h,s,d] roped K
__device__ float g_vh[BH * S_LEN * D_DIM];   // [b,h,s,d] V
__device__ float g_qn[BH * S_LEN];           // ||q||^2 per row
__device__ float g_kn[BH * S_LEN];           // ||k||^2 per row
__device__ float g_ctx[NTOK * HD];           // [b,s,h*64+d] attention output
__device__ float g_freq[32];                 // RoPE frequencies

// XOR-swizzled smem index for a 64-col fp32 tile: element (row, d).
// 16B chunk index (d>>2) is XORed with (row>>2) -> conflict-free float4
// reads along both rows-at-fixed-d and d-at-fixed-row access patterns.
__device__ __forceinline__ int swi(int row, int d) {
    return (row << 6) + ((((d >> 2) ^ (row >> 2)) & 15) << 2) + (d & 3);
}

// ---------------------------------------------------------------------------
// Kernel 0: RoPE frequency table (double-precision, rounded to fp32)
// ---------------------------------------------------------------------------
__global__ void init_freq_kernel() {
    int i = threadIdx.x;
    if (i < 32) {
        g_freq[i] = (float)(1.0 / pow(10000.0, (double)(2 * i) / 64.0));
    }
}

// ---------------------------------------------------------------------------
// Kernel 1: projections  qh/kh/vh = x @ W^T  (+ RoPE on q,k)
// grid.x = 64 row tiles (of NTOK), grid.y = 24 (w*8 + h), block = 256
// ---------------------------------------------------------------------------
__global__ __launch_bounds__(256) void proj_kernel(
    const float* __restrict__ x,
    const float* __restrict__ Wq,
    const float* __restrict__ Wk,
    const float* __restrict__ Wv)
{
    __shared__ float As[64 * 64];
    __shared__ float Bs[64 * 64];

    const int tid = threadIdx.x;
    const int tx  = tid & 15;
    const int ty  = tid >> 4;
    const int n0  = blockIdx.x * 64;
    const int w   = blockIdx.y >> 3;     // 0:q 1:k 2:v
    const int h   = blockIdx.y & 7;

    const float* W = (w == 0) ? Wq : (w == 1 ? Wk : Wv);

    // load A (64 tokens x 64 in-dims) and B (64 out-cols of head h x 64)
    for (int t = tid; t < 1024; t += 256) {
        int row = t >> 4, cd = t & 15;
        float4 a = *(const float4*)(x + (size_t)(n0 + row) * 64 + cd * 4);
        *(float4*)(As + (row << 6) + (((cd ^ (row >> 2)) & 15) << 2)) = a;
        float4 b = *(const float4*)(W + (size_t)(h * 64 + row) * 64 + cd * 4);
        *(float4*)(Bs + (row << 6) + (((cd ^ (row >> 2)) & 15) << 2)) = b;
    }
    __syncthreads();

    float s[4][4] = {};
    #pragma unroll
    for (int d0 = 0; d0 < 64; d0 += 4) {
        float4 av[4], bv[4];
        #pragma unroll
        for (int r = 0; r < 4; r++) av[r] = *(const float4*)(As + swi(4 * ty + r, d0));
        #pragma unroll
        for (int c = 0; c < 4; c++) bv[c] = *(const float4*)(Bs + swi(4 * tx + c, d0));
        #pragma unroll
        for (int r = 0; r < 4; r++) {
            #pragma unroll
            for (int c = 0; c < 4; c++) {
                s[r][c] += av[r].x * bv[c].x;
                s[r][c] += av[r].y * bv[c].y;
                s[r][c] += av[r].z * bv[c].z;
                s[r][c] += av[r].w * bv[c].w;
            }
        }
    }

    float* dst = (w == 0) ? g_qh : (w == 1 ? g_kh : g_vh);
    const float f0 = g_freq[2 * tx];
    const float f1 = g_freq[2 * tx + 1];

    #pragma unroll
    for (int r = 0; r < 4; r++) {
        int n  = n0 + 4 * ty + r;
        int b  = n >> 11;       // token -> batch
        int sp = n & 2047;      // token -> seq position
        float4 o;
        if (w < 2) {
            // RoPE: cols 4tx..4tx+3 = dims within head -> pairs (2tx),(2tx+1)
            float s0, c0, s1, c1;
            sincosf((float)sp * f0, &s0, &c0);
            sincosf((float)sp * f1, &s1, &c1);
            o.x = s[r][0] * c0 - s[r][1] * s0;
            o.y = s[r][0] * s0 + s[r][1] * c0;
            o.z = s[r][2] * c1 - s[r][3] * s1;
            o.w = s[r][2] * s1 + s[r][3] * c1;
        } else {
            o.x = s[r][0]; o.y = s[r][1]; o.z = s[r][2]; o.w = s[r][3];
        }
        *(float4*)(dst + ((size_t)(b * N_HEADS + h) * S_LEN + sp) * 64 + 4 * tx) = o;
    }
}

// ---------------------------------------------------------------------------
// Kernel 2: row norms of roped q/k.  65536 rows total (q then k).
// ---------------------------------------------------------------------------
__global__ void norm_kernel() {
    int gid = blockIdx.x * blockDim.x + threadIdx.x;
    int t   = gid >> 15;           // 0 -> q, 1 -> k
    int row = gid & 32767;
    const float* p = (t ? g_kh : g_qh) + (size_t)row * 64;
    float s = 0.f;
    #pragma unroll
    for (int i = 0; i < 16; i++) {
        float4 v = *(const float4*)(p + 4 * i);
        s += v.x * v.x + v.y * v.y + v.z * v.z + v.w * v.w;
    }
    (t ? g_kn : g_qn)[row] = s;
}

// ---------------------------------------------------------------------------
// Kernel 3: attention.  One block = one (bh, 64-row query tile).
// Causal loop over 64-key tiles; QK^T GEMM -> dist -> exp -> PV GEMM.
// Dynamic smem: Qs|Ks|Vs|Ps = 4 x 4096 floats = 64 KB.
// Heavy tiles scheduled first (bx>>4 = 0 -> qt = 31).
// ---------------------------------------------------------------------------
__global__ __launch_bounds__(256) void attn_kernel(const float* __restrict__ gamma) {
    extern __shared__ float sm[];
    float* Qs = sm;
    float* Ks = sm + 4096;
    float* Vs = sm + 8192;
    float* Ps = sm + 12288;

    const int tid = threadIdx.x;
    const int tx  = tid & 15;
    const int ty  = tid >> 4;
    const int bx  = blockIdx.x;
    const int bh  = bx & 15;
    const int qt  = 31 - (bx >> 4);          // heavy (long-causal) tiles first
    const int h   = bh & 7;

    const float g = gamma[h] * SCALE_F;
    const size_t base = (size_t)bh * S_LEN * 64;

    // load Q tile (swizzled)
    for (int t = tid; t < 1024; t += 256) {
        int row = t >> 4, cd = t & 15;
        float4 a = *(const float4*)(g_qh + base + (size_t)(qt * 64 + row) * 64 + cd * 4);
        *(float4*)(Qs + (row << 6) + (((cd ^ (row >> 2)) & 15) << 2)) = a;
    }
    float qnr[4];
    #pragma unroll
    for (int r = 0; r < 4; r++)
        qnr[r] = g_qn[bh * S_LEN + qt * 64 + 4 * ty + r];

    float acc[4][4] = {};

    for (int kt = 0; kt <= qt; kt++) {
        __syncthreads();   // previous iter's PV reads done before overwrite
        for (int t = tid; t < 1024; t += 256) {
            int row = t >> 4, cd = t & 15;
            int sidx = (row << 6) + (((cd ^ (row >> 2)) & 15) << 2);
            float4 a = *(const float4*)(g_kh + base + (size_t)(kt * 64 + row) * 64 + cd * 4);
            *(float4*)(Ks + sidx) = a;
            float4 b = *(const float4*)(g_vh + base + (size_t)(kt * 64 + row) * 64 + cd * 4);
            *(float4*)(Vs + sidx) = b;
        }
        float knc[4];
        #pragma unroll
        for (int c = 0; c < 4; c++)
            knc[c] = g_kn[bh * S_LEN + kt * 64 + 4 * tx + c];
        __syncthreads();

        // --- GEMM1: S = Q K^T (64x64x64) ---
        float s[4][4] = {};
        #pragma unroll
        for (int d0 = 0; d0 < 64; d0 += 4) {
            float4 qv[4], kv[4];
            #pragma unroll
            for (int r = 0; r < 4; r++) qv[r] = *(const float4*)(Qs + swi(4 * ty + r, d0));
            #pragma unroll
            for (int c = 0; c < 4; c++) kv[c] = *(const float4*)(Ks + swi(4 * tx + c, d0));
            #pragma unroll
            for (int r = 0; r < 4; r++) {
                #pragma unroll
                for (int c = 0; c < 4; c++) {
                    s[r][c] += qv[r].x * kv[c].x;
                    s[r][c] += qv[r].y * kv[c].y;
                    s[r][c] += qv[r].z * kv[c].z;
                    s[r][c] += qv[r].w * kv[c].w;
                }
            }
        }

        // --- dist / exp / causal mask -> Ps (stored transposed [j][i], swizzled) ---
        const bool diag = (kt == qt);
        #pragma unroll
        for (int c = 0; c < 4; c++) {
            int j = 4 * tx + c;
            #pragma unroll
            for (int r = 0; r < 4; r++) {
                float dd = fmaxf(qnr[r] - 2.0f * s[r][c] + knc[c], 0.0f);
                float p  = __expf(-g * dd);
                if (diag && (j > 4 * ty + r)) p = 0.0f;
                Ps[(j << 6) + (((ty ^ tx) & 15) << 2) + r] = p;
            }
        }
        __syncthreads();

        // --- GEMM2: acc += P V (64x64x64) ---
        #pragma unroll 16
        for (int j = 0; j < 64; j++) {
            float4 pv = *(const float4*)(Ps + (j << 6) + (((ty ^ (j >> 2)) & 15) << 2));
            float4 vv = *(const float4*)(Vs + (j << 6) + (((tx ^ (j >> 2)) & 15) << 2));
            acc[0][0] += pv.x * vv.x; acc[0][1] += pv.x * vv.y;
            acc[0][2] += pv.x * vv.z; acc[0][3] += pv.x * vv.w;
            acc[1][0] += pv.y * vv.x; acc[1][1] += pv.y * vv.y;
            acc[1][2] += pv.y * vv.z; acc[1][3] += pv.y * vv.w;
            acc[2][0] += pv.z * vv.x; acc[2][1] += pv.z * vv.y;
            acc[2][2] += pv.z * vv.z; acc[2][3] += pv.z * vv.w;
            acc[3][0] += pv.w * vv.x; acc[3][1] += pv.w * vv.y;
            acc[3][2] += pv.w * vv.z; acc[3][3] += pv.w * vv.w;
        }
    }

    // write ctx in [b, s, h*64+d] layout for the output GEMM
    const int b = bh >> 3;
    #pragma unroll
    for (int r = 0; r < 4; r++) {
        int sp = qt * 64 + 4 * ty + r;
        float4 o;
        o.x = acc[r][0]; o.y = acc[r][1]; o.z = acc[r][2]; o.w = acc[r][3];
        *(float4*)(g_ctx + ((size_t)(b * S_LEN + sp) * HD) + h * 64 + 4 * tx) = o;
    }
}

// ---------------------------------------------------------------------------
// Kernel 4: out = ctx @ Wo^T   (4096x64, K=512).  BM=32 -> 128 blocks.
// ---------------------------------------------------------------------------
__global__ __launch_bounds__(256) void out_kernel(
    const float* __restrict__ Wo, float* __restrict__ out)
{
    __shared__ float As[32 * 64];
    __shared__ float Bs[64 * 64];

    const int tid = threadIdx.x;
    const int tx  = tid & 15;
    const int ty  = tid >> 4;
    const int n0  = blockIdx.x * 32;

    float acc[2][4] = {};

    for (int c0 = 0; c0 < 512; c0 += 64) {
        __syncthreads();
        for (int t = tid; t < 512; t += 256) {
            int row = t >> 4, cd = t & 15;
            float4 a = *(const float4*)(g_ctx + (size_t)(n0 + row) * HD + c0 + cd * 4);
            *(float4*)(As + (row << 6) + (((cd ^ (row >> 2)) & 15) << 2)) = a;
        }
        for (int t = tid; t < 1024; t += 256) {
            int row = t >> 4, cd = t & 15;
            float4 b = *(const float4*)(Wo + (size_t)row * 512 + c0 + cd * 4);
            *(float4*)(Bs + (row << 6) + (((cd ^ (row >> 2)) & 15) << 2)) = b;
        }
        __syncthreads();

        #pragma unroll
        for (int d0 = 0; d0 < 64; d0 += 4) {
            float4 av[2], bv[4];
            av[0] = *(const float4*)(As + swi(2 * ty,     d0));
            av[1] = *(const float4*)(As + swi(2 * ty + 1, d0));
            #pragma unroll
            for (int c = 0; c < 4; c++) bv[c] = *(const float4*)(Bs + swi(4 * tx + c, d0));
            #pragma unroll
            for (int r = 0; r < 2; r++) {
                #pragma unroll
                for (int c = 0; c < 4; c++) {
                    acc[r][c] += av[r].x * bv[c].x;
                    acc[r][c] += av[r].y * bv[c].y;
                    acc[r][c] += av[r].z * bv[c].z;
                    acc[r][c] += av[r].w * bv[c].w;
                }
            }
        }
    }

    #pragma unroll
    for (int r = 0; r < 2; r++) {
        float4 o;
        o.x = acc[r][0]; o.y = acc[r][1]; o.z = acc[r][2]; o.w = acc[r][3];
        *(float4*)(out + (size_t)(n0 + 2 * ty + r) * 64 + 4 * tx) = o;
    }
}

// ---------------------------------------------------------------------------
// Launch
// ---------------------------------------------------------------------------
extern "C" void kernel_launch(void* const* d_in, const int* in_sizes, int n_in,
                              void* d_out, int out_size)
{
    const float* q     = (const float*)d_in[0];
    const float* Wq    = (const float*)d_in[1];
    const float* Wk    = (const float*)d_in[2];
    const float* Wv    = (const float*)d_in[3];
    const float* Wo    = (const float*)d_in[4];
    const float* gamma = (const float*)d_in[5];
    float* out = (float*)d_out;

    const int attn_smem = 4 * 4096 * (int)sizeof(float);  // 64 KB
    cudaFuncSetAttribute(attn_kernel,
                         cudaFuncAttributeMaxDynamicSharedMemorySize, attn_smem);

    init_freq_kernel<<<1, 32>>>();
    proj_kernel<<<dim3(64, 24), 256>>>(q, Wq, Wk, Wv);
    norm_kernel<<<256, 256>>>();
    attn_kernel<<<512, 256, attn_smem>>>(gamma);
    out_kernel<<<128, 256>>>(Wo, out);
}

// round 11
// speedup vs baseline: 1.0947x; 1.0947x over previous
#include <cuda_runtime.h>
#include <math.h>
#include <stdint.h>

// ---------------------------------------------------------------------------
// Problem constants
// ---------------------------------------------------------------------------
#define S_LEN   2048
#define D_DIM   64
#define N_HEADS 8
#define B_SZ    2
#define BH      (B_SZ * N_HEADS)          // 16
#define NTOK    (B_SZ * S_LEN)            // 4096
#define HD      (N_HEADS * D_DIM)         // 512
#define SCALE_F 0.125f                    // 1/sqrt(64)

typedef unsigned long long ull;

// ---------------------------------------------------------------------------
// Scratch (device globals -- no allocations allowed)
// ---------------------------------------------------------------------------
__device__ float g_qh[BH * S_LEN * D_DIM];   // [b,h,s,d] roped Q
__device__ float g_kh[BH * S_LEN * D_DIM];   // [b,h,s,d] roped K
__device__ float g_vh[BH * S_LEN * D_DIM];   // [b,h,s,d] V
__device__ float g_qn[BH * S_LEN];           // ||q||^2 per row
__device__ float g_kn[BH * S_LEN];           // ||k||^2 per row
__device__ float g_ctx[NTOK * HD];           // [b,s,h*64+d] attention output
__device__ float g_freq[32];                 // RoPE frequencies

// ---------------------------------------------------------------------------
// f32x2 packed-FMA helpers (Blackwell FFMA2 path -- 2 fp32 FMA per issue)
// ---------------------------------------------------------------------------
__device__ __forceinline__ ull fma2(ull a, ull b, ull c) {
    ull d;
    asm("fma.rn.f32x2 %0, %1, %2, %3;" : "=l"(d) : "l"(a), "l"(b), "l"(c));
    return d;
}
__device__ __forceinline__ float f2lo(ull x) { return __uint_as_float((unsigned)x); }
__device__ __forceinline__ float f2hi(ull x) { return __uint_as_float((unsigned)(x >> 32)); }

// cp.async 16B (L2-cached path; data is L2-resident)
__device__ __forceinline__ void cpa16(uint32_t s, const void* g) {
    asm volatile("cp.async.cg.shared.global [%0], [%1], 16;" :: "r"(s), "l"(g));
}

// XOR-swizzled smem index for a 64-col fp32 tile: element (row, d).
__device__ __forceinline__ int swi(int row, int d) {
    return (row << 6) + ((((d >> 2) ^ (row >> 2)) & 15) << 2) + (d & 3);
}

// ---------------------------------------------------------------------------
// Kernel 0: RoPE frequency table
// ---------------------------------------------------------------------------
__global__ void init_freq_kernel() {
    int i = threadIdx.x;
    if (i < 32) {
        g_freq[i] = (float)(1.0 / pow(10000.0, (double)(2 * i) / 64.0));
    }
}

// ---------------------------------------------------------------------------
// Kernel 1: projections  qh/kh/vh = x @ W^T  (+ RoPE on q,k), f32x2 inner
// ---------------------------------------------------------------------------
__global__ __launch_bounds__(256) void proj_kernel(
    const float* __restrict__ x,
    const float* __restrict__ Wq,
    const float* __restrict__ Wk,
    const float* __restrict__ Wv)
{
    __shared__ float As[64 * 64];
    __shared__ float Bs[64 * 64];

    const int tid = threadIdx.x;
    const int tx  = tid & 15;
    const int ty  = tid >> 4;
    const int n0  = blockIdx.x * 64;
    const int w   = blockIdx.y >> 3;     // 0:q 1:k 2:v
    const int h   = blockIdx.y & 7;

    const float* W = (w == 0) ? Wq : (w == 1 ? Wk : Wv);

    for (int t = tid; t < 1024; t += 256) {
        int row = t >> 4, cd = t & 15;
        float4 a = *(const float4*)(x + (size_t)(n0 + row) * 64 + cd * 4);
        *(float4*)(As + (row << 6) + (((cd ^ (row >> 2)) & 15) << 2)) = a;
        float4 b = *(const float4*)(W + (size_t)(h * 64 + row) * 64 + cd * 4);
        *(float4*)(Bs + (row << 6) + (((cd ^ (row >> 2)) & 15) << 2)) = b;
    }
    __syncthreads();

    ull s2[4][4] = {};
    #pragma unroll
    for (int d0 = 0; d0 < 64; d0 += 4) {
        ulonglong2 av[4], bv[4];
        #pragma unroll
        for (int r = 0; r < 4; r++) av[r] = *(const ulonglong2*)(As + swi(4 * ty + r, d0));
        #pragma unroll
        for (int c = 0; c < 4; c++) bv[c] = *(const ulonglong2*)(Bs + swi(4 * tx + c, d0));
        #pragma unroll
        for (int r = 0; r < 4; r++) {
            #pragma unroll
            for (int c = 0; c < 4; c++) {
                s2[r][c] = fma2(av[r].x, bv[c].x, s2[r][c]);
                s2[r][c] = fma2(av[r].y, bv[c].y, s2[r][c]);
            }
        }
    }

    float s[4][4];
    #pragma unroll
    for (int r = 0; r < 4; r++)
        #pragma unroll
        for (int c = 0; c < 4; c++)
            s[r][c] = f2lo(s2[r][c]) + f2hi(s2[r][c]);

    float* dst = (w == 0) ? g_qh : (w == 1 ? g_kh : g_vh);
    const float f0 = g_freq[2 * tx];
    const float f1 = g_freq[2 * tx + 1];

    #pragma unroll
    for (int r = 0; r < 4; r++) {
        int n  = n0 + 4 * ty + r;
        int b  = n >> 11;
        int sp = n & 2047;
        float4 o;
        if (w < 2) {
            float s0, c0, s1, c1;
            sincosf((float)sp * f0, &s0, &c0);
            sincosf((float)sp * f1, &s1, &c1);
            o.x = s[r][0] * c0 - s[r][1] * s0;
            o.y = s[r][0] * s0 + s[r][1] * c0;
            o.z = s[r][2] * c1 - s[r][3] * s1;
            o.w = s[r][2] * s1 + s[r][3] * c1;
        } else {
            o.x = s[r][0]; o.y = s[r][1]; o.z = s[r][2]; o.w = s[r][3];
        }
        *(float4*)(dst + ((size_t)(b * N_HEADS + h) * S_LEN + sp) * 64 + 4 * tx) = o;
    }
}

// ---------------------------------------------------------------------------
// Kernel 2: row norms of roped q/k
// ---------------------------------------------------------------------------
__global__ void norm_kernel() {
    int gid = blockIdx.x * blockDim.x + threadIdx.x;
    int t   = gid >> 15;
    int row = gid & 32767;
    const float* p = (t ? g_kh : g_qh) + (size_t)row * 64;
    float s = 0.f;
    #pragma unroll
    for (int i = 0; i < 16; i++) {
        float4 v = *(const float4*)(p + 4 * i);
        s += v.x * v.x + v.y * v.y + v.z * v.z + v.w * v.w;
    }
    (t ? g_kn : g_qn)[row] = s;
}

// ---------------------------------------------------------------------------
// Kernel 3: attention, f32x2 GEMMs + cp.async double-buffered K/V.
// smem (floats): Qs[4096] Ks0[4096] Ks1[4096] Vs0[4096] Vs1[4096] Ps[8192]
//   = 28672 floats = 112 KB.
// Ps stores duplicated score pairs (p,p) at  j*128 + (2i ^ ((j>>2)<<1))
//   -> GEMM2 reads dup-pairs with one broadcast LDS.128 per 2 rows.
// ---------------------------------------------------------------------------
#define PS_OFF 20480

__device__ __forceinline__ void prefetch_kv(uint32_t ks_s, uint32_t vs_s,
                                            const float* kg, const float* vg,
                                            int tid)
{
    #pragma unroll
    for (int it = 0; it < 4; it++) {
        int t   = tid + it * 256;
        int row = t >> 4, cd = t & 15;
        uint32_t sidx = (uint32_t)((row << 6) + (((cd ^ (row >> 2)) & 15) << 2)) * 4u;
        cpa16(ks_s + sidx, kg + (size_t)row * 64 + cd * 4);
        cpa16(vs_s + sidx, vg + (size_t)row * 64 + cd * 4);
    }
    asm volatile("cp.async.commit_group;");
}

__global__ __launch_bounds__(256) void attn_kernel(const float* __restrict__ gamma) {
    extern __shared__ float sm[];
    float* Qs = sm;
    float* Ps = sm + PS_OFF;

    const int tid = threadIdx.x;
    const int tx  = tid & 15;
    const int ty  = tid >> 4;
    const int bx  = blockIdx.x;
    const int bh  = bx & 15;
    const int qt  = 31 - (bx >> 4);          // heavy (long-causal) tiles first
    const int h   = bh & 7;

    const float g   = gamma[h] * SCALE_F;
    const size_t base = (size_t)bh * S_LEN * 64;

    uint32_t ks_s[2], vs_s[2];
    ks_s[0] = (uint32_t)__cvta_generic_to_shared(sm + 4096);
    ks_s[1] = (uint32_t)__cvta_generic_to_shared(sm + 8192);
    vs_s[0] = (uint32_t)__cvta_generic_to_shared(sm + 12288);
    vs_s[1] = (uint32_t)__cvta_generic_to_shared(sm + 16384);

    // kick off K/V prefetch for tile 0, then load Q behind it
    prefetch_kv(ks_s[0], vs_s[0], g_kh + base, g_vh + base, tid);

    for (int it = 0; it < 4; it++) {
        int t   = tid + it * 256;
        int row = t >> 4, cd = t & 15;
        float4 a = *(const float4*)(g_qh + base + (size_t)(qt * 64 + row) * 64 + cd * 4);
        *(float4*)(Qs + (row << 6) + (((cd ^ (row >> 2)) & 15) << 2)) = a;
    }
    float qnr[4];
    #pragma unroll
    for (int r = 0; r < 4; r++)
        qnr[r] = g_qn[bh * S_LEN + qt * 64 + 4 * ty + r];

    ull acc2[4][2] = {};   // [r][cpair]: packed (out[r][2cp], out[r][2cp+1])

    for (int kt = 0; kt <= qt; kt++) {
        const int st = kt & 1;
        __syncthreads();                       // prev GEMM2 reads of st^1 done
        if (kt < qt)
            prefetch_kv(ks_s[st ^ 1], vs_s[st ^ 1],
                        g_kh + base + (size_t)(kt + 1) * 64 * 64,
                        g_vh + base + (size_t)(kt + 1) * 64 * 64, tid);

        float knc[4];
        #pragma unroll
        for (int c = 0; c < 4; c++)
            knc[c] = g_kn[bh * S_LEN + kt * 64 + 4 * tx + c];

        if (kt < qt) asm volatile("cp.async.wait_group 1;");
        else         asm volatile("cp.async.wait_group 0;");
        __syncthreads();                       // make K/V (and Q on kt=0) visible

        const float* Kst = sm + 4096  + st * 4096;
        const float* Vst = sm + 12288 + st * 4096;

        // --- GEMM1: S = Q K^T (64x64x64), f32x2 packed along k ---
        ull acc1[4][4] = {};
        #pragma unroll
        for (int d0 = 0; d0 < 64; d0 += 4) {
            ulonglong2 qv[4], kv[4];
            #pragma unroll
            for (int r = 0; r < 4; r++) qv[r] = *(const ulonglong2*)(Qs  + swi(4 * ty + r, d0));
            #pragma unroll
            for (int c = 0; c < 4; c++) kv[c] = *(const ulonglong2*)(Kst + swi(4 * tx + c, d0));
            #pragma unroll
            for (int r = 0; r < 4; r++) {
                #pragma unroll
                for (int c = 0; c < 4; c++) {
                    acc1[r][c] = fma2(qv[r].x, kv[c].x, acc1[r][c]);
                    acc1[r][c] = fma2(qv[r].y, kv[c].y, acc1[r][c]);
                }
            }
        }

        // --- dist / exp / causal -> duplicated-pair Ps layout ---
        const bool diag = (kt == qt);
        #pragma unroll
        for (int c = 0; c < 4; c++) {
            const int j  = 4 * tx + c;
            const int X  = tx << 1;                 // ((j>>2)&15)<<1
            float* prow  = Ps + j * 128;
            #pragma unroll
            for (int r = 0; r < 4; r++) {
                float sfull = f2lo(acc1[r][c]) + f2hi(acc1[r][c]);
                float dd = fmaxf(fmaf(-2.0f, sfull, qnr[r] + knc[c]), 0.0f);
                float p  = __expf(-g * dd);
                if (diag && (j > 4 * ty + r)) p = 0.0f;
                int i   = 4 * ty + r;
                int pos = (2 * i) ^ X;
                *(float2*)(prow + pos) = make_float2(p, p);
            }
        }
        __syncthreads();

        // --- GEMM2: acc += P V (64x64x64), f32x2 packed along rows ---
        #pragma unroll 4
        for (int jo = 0; jo < 16; jo++) {
            const int s4 = jo & 3;                 // compile-time per unrolled body
            const int X24 = (s4 << 3) & 24;        // (X & 24) with X = (jo&15)<<1 ... see below
            // NOTE: X = ((j>>2)&15)<<1 = (jo&15)<<1 ; X&24 depends on jo bits 2-3:
            const int Xhi = ((jo & 12) << 1);      // bits 3-4 of X
            const int B   = (8 * ty) ^ Xhi;
            (void)X24;
            #pragma unroll
            for (int jj = 0; jj < 4; jj++) {
                const int j = jo * 4 + jj;
                const float* pb = Ps + j * 128 + B;
                ulonglong2 P0 = *(const ulonglong2*)(pb);
                ulonglong2 P1 = *(const ulonglong2*)(pb + 4);
                ulonglong2 vv = *(const ulonglong2*)(sm + 12288 + st * 4096
                                    + (j << 6) + (((tx ^ (j >> 2)) & 15) << 2));
                // pair slot u holds row r = u ^ s4
                acc2[0 ^ s4][0] = fma2(P0.x, vv.x, acc2[0 ^ s4][0]);
                acc2[0 ^ s4][1] = fma2(P0.x, vv.y, acc2[0 ^ s4][1]);
                acc2[1 ^ s4][0] = fma2(P0.y, vv.x, acc2[1 ^ s4][0]);
                acc2[1 ^ s4][1] = fma2(P0.y, vv.y, acc2[1 ^ s4][1]);
                acc2[2 ^ s4][0] = fma2(P1.x, vv.x, acc2[2 ^ s4][0]);
                acc2[2 ^ s4][1] = fma2(P1.x, vv.y, acc2[2 ^ s4][1]);
                acc2[3 ^ s4][0] = fma2(P1.y, vv.x, acc2[3 ^ s4][0]);
                acc2[3 ^ s4][1] = fma2(P1.y, vv.y, acc2[3 ^ s4][1]);
            }
        }
        (void)Vst;
    }

    // write ctx in [b, s, h*64+d] layout
    const int b = bh >> 3;
    #pragma unroll
    for (int r = 0; r < 4; r++) {
        int sp = qt * 64 + 4 * ty + r;
        float4 o;
        o.x = f2lo(acc2[r][0]); o.y = f2hi(acc2[r][0]);
        o.z = f2lo(acc2[r][1]); o.w = f2hi(acc2[r][1]);
        *(float4*)(g_ctx + ((size_t)(b * S_LEN + sp) * HD) + h * 64 + 4 * tx) = o;
    }
}

// ---------------------------------------------------------------------------
// Kernel 4: out = ctx @ Wo^T   (4096x64, K=512), f32x2 inner
// ---------------------------------------------------------------------------
__global__ __launch_bounds__(256) void out_kernel(
    const float* __restrict__ Wo, float* __restrict__ out)
{
    __shared__ float As[32 * 64];
    __shared__ float Bs[64 * 64];

    const int tid = threadIdx.x;
    const int tx  = tid & 15;
    const int ty  = tid >> 4;
    const int n0  = blockIdx.x * 32;

    ull a2[2][4] = {};

    for (int c0 = 0; c0 < 512; c0 += 64) {
        __syncthreads();
        for (int t = tid; t < 512; t += 256) {
            int row = t >> 4, cd = t & 15;
            float4 a = *(const float4*)(g_ctx + (size_t)(n0 + row) * HD + c0 + cd * 4);
            *(float4*)(As + (row << 6) + (((cd ^ (row >> 2)) & 15) << 2)) = a;
        }
        for (int t = tid; t < 1024; t += 256) {
            int row = t >> 4, cd = t & 15;
            float4 b = *(const float4*)(Wo + (size_t)row * 512 + c0 + cd * 4);
            *(float4*)(Bs + (row << 6) + (((cd ^ (row >> 2)) & 15) << 2)) = b;
        }
        __syncthreads();

        #pragma unroll
        for (int d0 = 0; d0 < 64; d0 += 4) {
            ulonglong2 av[2], bv[4];
            av[0] = *(const ulonglong2*)(As + swi(2 * ty,     d0));
            av[1] = *(const ulonglong2*)(As + swi(2 * ty + 1, d0));
            #pragma unroll
            for (int c = 0; c < 4; c++) bv[c] = *(const ulonglong2*)(Bs + swi(4 * tx + c, d0));
            #pragma unroll
            for (int r = 0; r < 2; r++) {
                #pragma unroll
                for (int c = 0; c < 4; c++) {
                    a2[r][c] = fma2(av[r].x, bv[c].x, a2[r][c]);
                    a2[r][c] = fma2(av[r].y, bv[c].y, a2[r][c]);
                }
            }
        }
    }

    #pragma unroll
    for (int r = 0; r < 2; r++) {
        float4 o;
        o.x = f2lo(a2[r][0]) + f2hi(a2[r][0]);
        o.y = f2lo(a2[r][1]) + f2hi(a2[r][1]);
        o.z = f2lo(a2[r][2]) + f2hi(a2[r][2]);
        o.w = f2lo(a2[r][3]) + f2hi(a2[r][3]);
        *(float4*)(out + (size_t)(n0 + 2 * ty + r) * 64 + 4 * tx) = o;
    }
}

// ---------------------------------------------------------------------------
// Launch
// ---------------------------------------------------------------------------
extern "C" void kernel_launch(void* const* d_in, const int* in_sizes, int n_in,
                              void* d_out, int out_size)
{
    const float* q     = (const float*)d_in[0];
    const float* Wq    = (const float*)d_in[1];
    const float* Wk    = (const float*)d_in[2];
    const float* Wv    = (const float*)d_in[3];
    const float* Wo    = (const float*)d_in[4];
    const float* gamma = (const float*)d_in[5];
    float* out = (float*)d_out;

    const int attn_smem = 28672 * (int)sizeof(float);  // 112 KB
    cudaFuncSetAttribute(attn_kernel,
                         cudaFuncAttributeMaxDynamicSharedMemorySize, attn_smem);

    init_freq_kernel<<<1, 32>>>();
    proj_kernel<<<dim3(64, 24), 256>>>(q, Wq, Wk, Wv);
    norm_kernel<<<256, 256>>>();
    attn_kernel<<<512, 256, attn_smem>>>(gamma);
    out_kernel<<<128, 256>>>(Wo, out);
}

// round 12
// speedup vs baseline: 1.1591x; 1.0589x over previous
#include <cuda_runtime.h>
#include <math.h>
#include <stdint.h>

// ---------------------------------------------------------------------------
// Problem constants
// ---------------------------------------------------------------------------
#define S_LEN   2048
#define D_DIM   64
#define N_HEADS 8
#define B_SZ    2
#define BH      (B_SZ * N_HEADS)          // 16
#define NTOK    (B_SZ * S_LEN)            // 4096
#define HD      (N_HEADS * D_DIM)         // 512
#define SCALE_F 0.125f                    // 1/sqrt(64)

typedef unsigned long long ull;

// ---------------------------------------------------------------------------
// Scratch (device globals -- no allocations allowed)
// ---------------------------------------------------------------------------
__device__ float g_qh[BH * S_LEN * D_DIM];   // [b,h,s,d] roped Q
__device__ float g_kh[BH * S_LEN * D_DIM];   // [b,h,s,d] roped K
__device__ float g_vh[BH * S_LEN * D_DIM];   // [b,h,s,d] V
__device__ float g_qn[BH * S_LEN];           // ||q||^2 per row
__device__ float g_kn[BH * S_LEN];           // ||k||^2 per row
__device__ float g_ctx[NTOK * HD];           // [b,s,h*64+d] attention output
__device__ float g_freq[32];                 // RoPE frequencies

// ---------------------------------------------------------------------------
// f32x2 packed-FMA helpers (Blackwell FFMA2 path -- 2 fp32 FMA per issue)
// ---------------------------------------------------------------------------
__device__ __forceinline__ ull fma2(ull a, ull b, ull c) {
    ull d;
    asm("fma.rn.f32x2 %0, %1, %2, %3;" : "=l"(d) : "l"(a), "l"(b), "l"(c));
    return d;
}
__device__ __forceinline__ float f2lo(ull x) { return __uint_as_float((unsigned)x); }
__device__ __forceinline__ float f2hi(ull x) { return __uint_as_float((unsigned)(x >> 32)); }

// cp.async 16B (L2-cached path; data is L2-resident)
__device__ __forceinline__ void cpa16(uint32_t s, const void* g) {
    asm volatile("cp.async.cg.shared.global [%0], [%1], 16;" :: "r"(s), "l"(g));
}

// XOR-swizzled smem index for a 64-col fp32 tile: element (row, d).
__device__ __forceinline__ int swi(int row, int d) {
    return (row << 6) + ((((d >> 2) ^ (row >> 2)) & 15) << 2) + (d & 3);
}

// ---------------------------------------------------------------------------
// Kernel 0: RoPE frequency table
// ---------------------------------------------------------------------------
__global__ void init_freq_kernel() {
    int i = threadIdx.x;
    if (i < 32) {
        g_freq[i] = (float)(1.0 / pow(10000.0, (double)(2 * i) / 64.0));
    }
}

// ---------------------------------------------------------------------------
// Kernel 1: projections  qh/kh/vh = x @ W^T  (+ RoPE on q,k), f32x2 inner
// ---------------------------------------------------------------------------
__global__ __launch_bounds__(256) void proj_kernel(
    const float* __restrict__ x,
    const float* __restrict__ Wq,
    const float* __restrict__ Wk,
    const float* __restrict__ Wv)
{
    __shared__ float As[64 * 64];
    __shared__ float Bs[64 * 64];

    const int tid = threadIdx.x;
    const int tx  = tid & 15;
    const int ty  = tid >> 4;
    const int n0  = blockIdx.x * 64;
    const int w   = blockIdx.y >> 3;     // 0:q 1:k 2:v
    const int h   = blockIdx.y & 7;

    const float* W = (w == 0) ? Wq : (w == 1 ? Wk : Wv);

    for (int t = tid; t < 1024; t += 256) {
        int row = t >> 4, cd = t & 15;
        float4 a = *(const float4*)(x + (size_t)(n0 + row) * 64 + cd * 4);
        *(float4*)(As + (row << 6) + (((cd ^ (row >> 2)) & 15) << 2)) = a;
        float4 b = *(const float4*)(W + (size_t)(h * 64 + row) * 64 + cd * 4);
        *(float4*)(Bs + (row << 6) + (((cd ^ (row >> 2)) & 15) << 2)) = b;
    }
    __syncthreads();

    ull s2[4][4] = {};
    #pragma unroll
    for (int d0 = 0; d0 < 64; d0 += 4) {
        ulonglong2 av[4], bv[4];
        #pragma unroll
        for (int r = 0; r < 4; r++) av[r] = *(const ulonglong2*)(As + swi(4 * ty + r, d0));
        #pragma unroll
        for (int c = 0; c < 4; c++) bv[c] = *(const ulonglong2*)(Bs + swi(4 * tx + c, d0));
        #pragma unroll
        for (int r = 0; r < 4; r++) {
            #pragma unroll
            for (int c = 0; c < 4; c++) {
                s2[r][c] = fma2(av[r].x, bv[c].x, s2[r][c]);
                s2[r][c] = fma2(av[r].y, bv[c].y, s2[r][c]);
            }
        }
    }

    float s[4][4];
    #pragma unroll
    for (int r = 0; r < 4; r++)
        #pragma unroll
        for (int c = 0; c < 4; c++)
            s[r][c] = f2lo(s2[r][c]) + f2hi(s2[r][c]);

    float* dst = (w == 0) ? g_qh : (w == 1 ? g_kh : g_vh);
    const float f0 = g_freq[2 * tx];
    const float f1 = g_freq[2 * tx + 1];

    #pragma unroll
    for (int r = 0; r < 4; r++) {
        int n  = n0 + 4 * ty + r;
        int b  = n >> 11;
        int sp = n & 2047;
        float4 o;
        if (w < 2) {
            float s0, c0, s1, c1;
            sincosf((float)sp * f0, &s0, &c0);
            sincosf((float)sp * f1, &s1, &c1);
            o.x = s[r][0] * c0 - s[r][1] * s0;
            o.y = s[r][0] * s0 + s[r][1] * c0;
            o.z = s[r][2] * c1 - s[r][3] * s1;
            o.w = s[r][2] * s1 + s[r][3] * c1;
        } else {
            o.x = s[r][0]; o.y = s[r][1]; o.z = s[r][2]; o.w = s[r][3];
        }
        *(float4*)(dst + ((size_t)(b * N_HEADS + h) * S_LEN + sp) * 64 + 4 * tx) = o;
    }
}

// ---------------------------------------------------------------------------
// Kernel 2: row norms of roped q/k
// ---------------------------------------------------------------------------
__global__ void norm_kernel() {
    int gid = blockIdx.x * blockDim.x + threadIdx.x;
    int t   = gid >> 15;
    int row = gid & 32767;
    const float* p = (t ? g_kh : g_qh) + (size_t)row * 64;
    float s = 0.f;
    #pragma unroll
    for (int i = 0; i < 16; i++) {
        float4 v = *(const float4*)(p + 4 * i);
        s += v.x * v.x + v.y * v.y + v.z * v.z + v.w * v.w;
    }
    (t ? g_kn : g_qn)[row] = s;
}

// ---------------------------------------------------------------------------
// Kernel 3: attention, f32x2 GEMMs + cp.async double-buffered K/V.
// smem (floats): Qs[4096] Ks0[4096] Ks1[4096] Vs0[4096] Vs1[4096] Ps[8192]
//   = 28672 floats = 112 KB.
// Ps stores duplicated score pairs (p,p) at  j*128 + (2i ^ ((j>>2)<<1))
//   -> GEMM2 reads dup-pairs with one broadcast LDS.128 per 2 rows.
// ---------------------------------------------------------------------------
#define PS_OFF 20480

__device__ __forceinline__ void prefetch_kv(uint32_t ks_s, uint32_t vs_s,
                                            const float* kg, const float* vg,
                                            int tid)
{
    #pragma unroll
    for (int it = 0; it < 4; it++) {
        int t   = tid + it * 256;
        int row = t >> 4, cd = t & 15;
        uint32_t sidx = (uint32_t)((row << 6) + (((cd ^ (row >> 2)) & 15) << 2)) * 4u;
        cpa16(ks_s + sidx, kg + (size_t)row * 64 + cd * 4);
        cpa16(vs_s + sidx, vg + (size_t)row * 64 + cd * 4);
    }
    asm volatile("cp.async.commit_group;");
}

__global__ __launch_bounds__(256) void attn_kernel(const float* __restrict__ gamma) {
    extern __shared__ float sm[];
    float* Qs = sm;
    float* Ps = sm + PS_OFF;

    const int tid = threadIdx.x;
    const int tx  = tid & 15;
    const int ty  = tid >> 4;
    const int bx  = blockIdx.x;
    const int bh  = bx & 15;
    const int qt  = 31 - (bx >> 4);          // heavy (long-causal) tiles first
    const int h   = bh & 7;

    const float g   = gamma[h] * SCALE_F;
    const size_t base = (size_t)bh * S_LEN * 64;

    uint32_t ks_s[2], vs_s[2];
    ks_s[0] = (uint32_t)__cvta_generic_to_shared(sm + 4096);
    ks_s[1] = (uint32_t)__cvta_generic_to_shared(sm + 8192);
    vs_s[0] = (uint32_t)__cvta_generic_to_shared(sm + 12288);
    vs_s[1] = (uint32_t)__cvta_generic_to_shared(sm + 16384);

    // kick off K/V prefetch for tile 0, then load Q behind it
    prefetch_kv(ks_s[0], vs_s[0], g_kh + base, g_vh + base, tid);

    for (int it = 0; it < 4; it++) {
        int t   = tid + it * 256;
        int row = t >> 4, cd = t & 15;
        float4 a = *(const float4*)(g_qh + base + (size_t)(qt * 64 + row) * 64 + cd * 4);
        *(float4*)(Qs + (row << 6) + (((cd ^ (row >> 2)) & 15) << 2)) = a;
    }
    float qnr[4];
    #pragma unroll
    for (int r = 0; r < 4; r++)
        qnr[r] = g_qn[bh * S_LEN + qt * 64 + 4 * ty + r];

    ull acc2[4][2] = {};   // [r][cpair]: packed (out[r][2cp], out[r][2cp+1])

    for (int kt = 0; kt <= qt; kt++) {
        const int st = kt & 1;
        __syncthreads();                       // prev GEMM2 reads of st^1 done
        if (kt < qt)
            prefetch_kv(ks_s[st ^ 1], vs_s[st ^ 1],
                        g_kh + base + (size_t)(kt + 1) * 64 * 64,
                        g_vh + base + (size_t)(kt + 1) * 64 * 64, tid);

        float knc[4];
        #pragma unroll
        for (int c = 0; c < 4; c++)
            knc[c] = g_kn[bh * S_LEN + kt * 64 + 4 * tx + c];

        if (kt < qt) asm volatile("cp.async.wait_group 1;");
        else         asm volatile("cp.async.wait_group 0;");
        __syncthreads();                       // make K/V (and Q on kt=0) visible

        const float* Kst = sm + 4096  + st * 4096;
        const float* Vst = sm + 12288 + st * 4096;

        // --- GEMM1: S = Q K^T (64x64x64), f32x2 packed along k ---
        ull acc1[4][4] = {};
        #pragma unroll
        for (int d0 = 0; d0 < 64; d0 += 4) {
            ulonglong2 qv[4], kv[4];
            #pragma unroll
            for (int r = 0; r < 4; r++) qv[r] = *(const ulonglong2*)(Qs  + swi(4 * ty + r, d0));
            #pragma unroll
            for (int c = 0; c < 4; c++) kv[c] = *(const ulonglong2*)(Kst + swi(4 * tx + c, d0));
            #pragma unroll
            for (int r = 0; r < 4; r++) {
                #pragma unroll
                for (int c = 0; c < 4; c++) {
                    acc1[r][c] = fma2(qv[r].x, kv[c].x, acc1[r][c]);
                    acc1[r][c] = fma2(qv[r].y, kv[c].y, acc1[r][c]);
                }
            }
        }

        // --- dist / exp / causal -> duplicated-pair Ps layout ---
        const bool diag = (kt == qt);
        #pragma unroll
        for (int c = 0; c < 4; c++) {
            const int j  = 4 * tx + c;
            const int X  = tx << 1;                 // ((j>>2)&15)<<1
            float* prow  = Ps + j * 128;
            #pragma unroll
            for (int r = 0; r < 4; r++) {
                float sfull = f2lo(acc1[r][c]) + f2hi(acc1[r][c]);
                float dd = fmaxf(fmaf(-2.0f, sfull, qnr[r] + knc[c]), 0.0f);
                float p  = __expf(-g * dd);
                if (diag && (j > 4 * ty + r)) p = 0.0f;
                int i   = 4 * ty + r;
                int pos = (2 * i) ^ X;
                *(float2*)(prow + pos) = make_float2(p, p);
            }
        }
        __syncthreads();

        // --- GEMM2: acc += P V (64x64x64), f32x2 packed along rows ---
        #pragma unroll 4
        for (int jo = 0; jo < 16; jo++) {
            const int s4 = jo & 3;                 // compile-time per unrolled body
            const int X24 = (s4 << 3) & 24;        // (X & 24) with X = (jo&15)<<1 ... see below
            // NOTE: X = ((j>>2)&15)<<1 = (jo&15)<<1 ; X&24 depends on jo bits 2-3:
            const int Xhi = ((jo & 12) << 1);      // bits 3-4 of X
            const int B   = (8 * ty) ^ Xhi;
            (void)X24;
            #pragma unroll
            for (int jj = 0; jj < 4; jj++) {
                const int j = jo * 4 + jj;
                const float* pb = Ps + j * 128 + B;
                ulonglong2 P0 = *(const ulonglong2*)(pb);
                ulonglong2 P1 = *(const ulonglong2*)(pb + 4);
                ulonglong2 vv = *(const ulonglong2*)(sm + 12288 + st * 4096
                                    + (j << 6) + (((tx ^ (j >> 2)) & 15) << 2));
                // pair slot u holds row r = u ^ s4
                acc2[0 ^ s4][0] = fma2(P0.x, vv.x, acc2[0 ^ s4][0]);
                acc2[0 ^ s4][1] = fma2(P0.x, vv.y, acc2[0 ^ s4][1]);
                acc2[1 ^ s4][0] = fma2(P0.y, vv.x, acc2[1 ^ s4][0]);
                acc2[1 ^ s4][1] = fma2(P0.y, vv.y, acc2[1 ^ s4][1]);
                acc2[2 ^ s4][0] = fma2(P1.x, vv.x, acc2[2 ^ s4][0]);
                acc2[2 ^ s4][1] = fma2(P1.x, vv.y, acc2[2 ^ s4][1]);
                acc2[3 ^ s4][0] = fma2(P1.y, vv.x, acc2[3 ^ s4][0]);
                acc2[3 ^ s4][1] = fma2(P1.y, vv.y, acc2[3 ^ s4][1]);
            }
        }
        (void)Vst;
    }

    // write ctx in [b, s, h*64+d] layout
    const int b = bh >> 3;
    #pragma unroll
    for (int r = 0; r < 4; r++) {
        int sp = qt * 64 + 4 * ty + r;
        float4 o;
        o.x = f2lo(acc2[r][0]); o.y = f2hi(acc2[r][0]);
        o.z = f2lo(acc2[r][1]); o.w = f2hi(acc2[r][1]);
        *(float4*)(g_ctx + ((size_t)(b * S_LEN + sp) * HD) + h * 64 + 4 * tx) = o;
    }
}

// ---------------------------------------------------------------------------
// Kernel 4: out = ctx @ Wo^T   (4096x64, K=512), f32x2 inner
// ---------------------------------------------------------------------------
__global__ __launch_bounds__(256) void out_kernel(
    const float* __restrict__ Wo, float* __restrict__ out)
{
    __shared__ float As[32 * 64];
    __shared__ float Bs[64 * 64];

    const int tid = threadIdx.x;
    const int tx  = tid & 15;
    const int ty  = tid >> 4;
    const int n0  = blockIdx.x * 32;

    ull a2[2][4] = {};

    for (int c0 = 0; c0 < 512; c0 += 64) {
        __syncthreads();
        for (int t = tid; t < 512; t += 256) {
            int row = t >> 4, cd = t & 15;
            float4 a = *(const float4*)(g_ctx + (size_t)(n0 + row) * HD + c0 + cd * 4);
            *(float4*)(As + (row << 6) + (((cd ^ (row >> 2)) & 15) << 2)) = a;
        }
        for (int t = tid; t < 1024; t += 256) {
            int row = t >> 4, cd = t & 15;
            float4 b = *(const float4*)(Wo + (size_t)row * 512 + c0 + cd * 4);
            *(float4*)(Bs + (row << 6) + (((cd ^ (row >> 2)) & 15) << 2)) = b;
        }
        __syncthreads();

        #pragma unroll
        for (int d0 = 0; d0 < 64; d0 += 4) {
            ulonglong2 av[2], bv[4];
            av[0] = *(const ulonglong2*)(As + swi(2 * ty,     d0));
            av[1] = *(const ulonglong2*)(As + swi(2 * ty + 1, d0));
            #pragma unroll
            for (int c = 0; c < 4; c++) bv[c] = *(const ulonglong2*)(Bs + swi(4 * tx + c, d0));
            #pragma unroll
            for (int r = 0; r < 2; r++) {
                #pragma unroll
                for (int c = 0; c < 4; c++) {
                    a2[r][c] = fma2(av[r].x, bv[c].x, a2[r][c]);
                    a2[r][c] = fma2(av[r].y, bv[c].y, a2[r][c]);
                }
            }
        }
    }

    #pragma unroll
    for (int r = 0; r < 2; r++) {
        float4 o;
        o.x = f2lo(a2[r][0]) + f2hi(a2[r][0]);
        o.y = f2lo(a2[r][1]) + f2hi(a2[r][1]);
        o.z = f2lo(a2[r][2]) + f2hi(a2[r][2]);
        o.w = f2lo(a2[r][3]) + f2hi(a2[r][3]);
        *(float4*)(out + (size_t)(n0 + 2 * ty + r) * 64 + 4 * tx) = o;
    }
}

// ---------------------------------------------------------------------------
// Launch
// ---------------------------------------------------------------------------
extern "C" void kernel_launch(void* const* d_in, const int* in_sizes, int n_in,
                              void* d_out, int out_size)
{
    const float* q     = (const float*)d_in[0];
    const float* Wq    = (const float*)d_in[1];
    const float* Wk    = (const float*)d_in[2];
    const float* Wv    = (const float*)d_in[3];
    const float* Wo    = (const float*)d_in[4];
    const float* gamma = (const float*)d_in[5];
    float* out = (float*)d_out;

    const int attn_smem = 28672 * (int)sizeof(float);  // 112 KB
    cudaFuncSetAttribute(attn_kernel,
                         cudaFuncAttributeMaxDynamicSharedMemorySize, attn_smem);

    init_freq_kernel<<<1, 32>>>();
    proj_kernel<<<dim3(64, 24), 256>>>(q, Wq, Wk, Wv);
    norm_kernel<<<256, 256>>>();
    attn_kernel<<<512, 256, attn_smem>>>(gamma);
    out_kernel<<<128, 256>>>(Wo, out);
}